// round 11
// baseline (speedup 1.0000x reference)
#include <cuda_runtime.h>
#include <cuda_bf16.h>
#include <cstdint>
#include <math.h>

#define BB    64
#define TT    512
#define DD    256
#define HH    512
#define TTBB  (TT * BB)     // 32768
#define NCTA  128
#define NGRP  64
#define NTH   256

// ---------------------------------------------------------------------------
// Global scratch
// ---------------------------------------------------------------------------
__device__ __nv_bfloat16 g_xhi[DD * TTBB];      // x planes [d][t][b]
__device__ __nv_bfloat16 g_xlo[DD * TTBB];
__device__ __nv_bfloat16 g_o0hi[HH * TTBB];     // layer0 out planes [h][t][b]
__device__ __nv_bfloat16 g_o0lo[HH * TTBB];
__device__ __nv_bfloat16 g_hhi[2 * HH * BB];    // h planes [buf][b][pk] PERMUTED
__device__ __nv_bfloat16 g_hlo[2 * HH * BB];
__device__ __nv_bfloat16 g_wih0hi[4 * HH * DD];
__device__ __nv_bfloat16 g_wih0lo[4 * HH * DD];
__device__ __nv_bfloat16 g_wih1hi[4 * HH * HH];
__device__ __nv_bfloat16 g_wih1lo[4 * HH * HH];
__device__ float g_xg0[(size_t)4 * HH * TTBB];
__device__ float g_xg1[(size_t)4 * HH * TTBB];
__device__ unsigned g_bar_count[2];
__device__ unsigned g_bar_epoch[2];

// ---------------------------------------------------------------------------
// Helpers
// ---------------------------------------------------------------------------
__device__ __forceinline__ void ldsm_x4(uint32_t (&r)[4], uint32_t addr) {
    asm volatile("ldmatrix.sync.aligned.m8n8.x4.shared.b16 {%0,%1,%2,%3}, [%4];\n"
                 : "=r"(r[0]), "=r"(r[1]), "=r"(r[2]), "=r"(r[3]) : "r"(addr));
}
__device__ __forceinline__ void ldsm_x2t(uint32_t (&r)[2], uint32_t addr) {
    asm volatile("ldmatrix.sync.aligned.m8n8.x2.trans.shared.b16 {%0,%1}, [%2];\n"
                 : "=r"(r[0]), "=r"(r[1]) : "r"(addr));
}
__device__ __forceinline__ void mma_bf16(float (&d)[4], const uint32_t (&a)[4],
                                         const uint32_t (&b)[2]) {
    asm volatile("mma.sync.aligned.m16n8k16.row.col.f32.bf16.bf16.f32 "
                 "{%0,%1,%2,%3}, {%4,%5,%6,%7}, {%8,%9}, {%0,%1,%2,%3};\n"
                 : "+f"(d[0]), "+f"(d[1]), "+f"(d[2]), "+f"(d[3])
                 : "r"(a[0]), "r"(a[1]), "r"(a[2]), "r"(a[3]),
                   "r"(b[0]), "r"(b[1]));
}
__device__ __forceinline__ void mma_bf16_2(float (&d)[4], const uint32_t (&a)[4],
                                           uint32_t b0, uint32_t b1) {
    asm volatile("mma.sync.aligned.m16n8k16.row.col.f32.bf16.bf16.f32 "
                 "{%0,%1,%2,%3}, {%4,%5,%6,%7}, {%8,%9}, {%0,%1,%2,%3};\n"
                 : "+f"(d[0]), "+f"(d[1]), "+f"(d[2]), "+f"(d[3])
                 : "r"(a[0]), "r"(a[1]), "r"(a[2]), "r"(a[3]),
                   "r"(b0), "r"(b1));
}
__device__ __forceinline__ void split_bf16(float v, __nv_bfloat16& hi, __nv_bfloat16& lo) {
    hi = __float2bfloat16_rn(v);
    lo = __float2bfloat16_rn(v - __bfloat162float(hi));
}
__device__ __forceinline__ void cp_async16(uint32_t dst, const void* src) {
    asm volatile("cp.async.cg.shared.global [%0], [%1], 16;\n" :: "r"(dst), "l"(src));
}
__device__ __forceinline__ void cp_commit() {
    asm volatile("cp.async.commit_group;\n");
}
template <int N>
__device__ __forceinline__ void cp_wait() {
    asm volatile("cp.async.wait_group %0;\n" :: "n"(N));
}

// permuted k index inside h rows: 16-blocks reordered (2m,2m+1,2m+8,2m+9)
__device__ __forceinline__ int pk_of(int k) {
    int r = k & 15;
    return (k & ~15) + (((r & 7) >> 1) << 2) + (((r >> 3) & 1) << 1) + (r & 1);
}

// ---------------------------------------------------------------------------
// Grouped grid barrier (64 CTAs per group, all co-resident)
// ---------------------------------------------------------------------------
__device__ __forceinline__ void grid_barrier(int tid, int grp, unsigned& target) {
    __threadfence();
    __syncthreads();
    target += 1;
    if (tid == 0) {
        unsigned old = atomicAdd(&g_bar_count[grp], 1u);
        if (old == NGRP - 1) {
            atomicExch(&g_bar_count[grp], 0u);
            __threadfence();
            atomicAdd(&g_bar_epoch[grp], 1u);
        } else {
            while ((int)(*(volatile unsigned*)&g_bar_epoch[grp] - target) < 0) {
                __nanosleep(32);
            }
            __threadfence();
        }
    }
    __syncthreads();
}

// ---------------------------------------------------------------------------
// Split fp32 weights into bf16 hi/lo planes
// ---------------------------------------------------------------------------
__global__ void split_w_kernel(const float* __restrict__ W,
                               __nv_bfloat16* __restrict__ hi,
                               __nv_bfloat16* __restrict__ lo, int n) {
    for (int i = blockIdx.x * blockDim.x + threadIdx.x; i < n; i += gridDim.x * blockDim.x) {
        __nv_bfloat16 h, l;
        split_bf16(W[i], h, l);
        hi[i] = h;
        lo[i] = l;
    }
}

// ---------------------------------------------------------------------------
// Transpose + split x: [b][t][d] -> planes [d][t][b]
// ---------------------------------------------------------------------------
__global__ void transpose_x_kernel(const float* __restrict__ x) {
    extern __shared__ float sm[];  // [256][65]
    const int t = blockIdx.x;
    const int tid = threadIdx.x;
    for (int i = tid; i < BB * DD; i += NTH) {
        int b = i >> 8;
        int d = i & 255;
        sm[d * 65 + b] = x[(size_t)b * (TT * DD) + (size_t)t * DD + d];
    }
    __syncthreads();
    for (int i = tid; i < DD * BB; i += NTH) {
        int d = i >> 6;
        int b = i & 63;
        float v = sm[d * 65 + b];
        __nv_bfloat16 hi, lo;
        split_bf16(v, hi, lo);
        const size_t idx = (size_t)d * TTBB + t * BB + b;
        g_xhi[idx] = hi;
        g_xlo[idx] = lo;
    }
}

// ---------------------------------------------------------------------------
// Bulk GEMM: C[j][n] = sum_k W[j][k] * X[k][n]  (unchanged from R10, proven)
// ---------------------------------------------------------------------------
template <int K>
__global__ __launch_bounds__(NTH)
void gemm_xg_kernel(const __nv_bfloat16* __restrict__ Whi,
                    const __nv_bfloat16* __restrict__ Wlo,
                    const __nv_bfloat16* __restrict__ Xhi,
                    const __nv_bfloat16* __restrict__ Xlo,
                    float* __restrict__ C) {
    constexpr int NKC = K / 32;
    extern __shared__ char sm_raw[];
    const uint32_t sbase = (uint32_t)__cvta_generic_to_shared(sm_raw);

    const int tid  = threadIdx.x;
    const int lane = tid & 31;
    const int w    = tid >> 5;
    const int wj   = w >> 2;
    const int wn0g = (w & 3) * 4;
    const int j0   = blockIdx.y * 128;
    const int n0   = blockIdx.x * 128;

    auto stage = [&](int kc, int buf) {
        const uint32_t bb = sbase + buf * 32768;
        #pragma unroll
        for (int q = 0; q < 4; ++q) {
            int idx = tid + q * 256;
            int p   = idx >> 9;
            int rem = idx & 511;
            int jl  = rem >> 2;
            int kh  = (rem >> 1) & 1;
            int g   = rem & 1;
            const __nv_bfloat16* src = (p ? Wlo : Whi)
                + (size_t)(j0 + jl) * K + kc * 32 + kh * 16 + g * 8;
            uint32_t dst = bb + p * 8192
                + (((jl >> 4) * 2 + kh) * 512)
                + (jl & 15) * 32
                + ((((unsigned)g) ^ (((unsigned)jl >> 2) & 1u)) << 4);
            cp_async16(dst, src);
        }
        #pragma unroll
        for (int q = 0; q < 4; ++q) {
            int idx = tid + q * 256;
            int p   = idx >> 9;
            int rem = idx & 511;
            int k   = rem >> 4;
            int g   = rem & 15;
            const __nv_bfloat16* src = (p ? Xlo : Xhi)
                + (size_t)(kc * 32 + k) * TTBB + n0 + g * 8;
            uint32_t dst = bb + 16384 + p * 8192 + k * 256
                + ((((unsigned)g) ^ ((unsigned)k & 7u)) << 4);
            cp_async16(dst, src);
        }
        cp_commit();
    };

    const uint32_t a_off = (uint32_t)((lane & 15) * 32
        + ((((unsigned)lane >> 4) ^ ((((unsigned)lane & 15) >> 2) & 1u)) << 4));

    float acc[4][4][4];
    #pragma unroll
    for (int mj = 0; mj < 4; ++mj)
        #pragma unroll
        for (int nj = 0; nj < 4; ++nj)
            #pragma unroll
            for (int q = 0; q < 4; ++q) acc[mj][nj][q] = 0.0f;

    stage(0, 0);
    for (int kc = 0; kc < NKC; ++kc) {
        if (kc + 1 < NKC) {
            stage(kc + 1, (kc + 1) & 1);
            cp_wait<1>();
        } else {
            cp_wait<0>();
        }
        __syncthreads();

        const uint32_t bb = sbase + (kc & 1) * 32768;
        const uint32_t Ahi_b = bb, Alo_b = bb + 8192;
        const uint32_t Bhi_b = bb + 16384, Blo_b = bb + 24576;

        #pragma unroll
        for (int kt = 0; kt < 2; ++kt) {
            uint32_t ahi[4][4], alo[4][4], bhi[4][2], blo[4][2];
            #pragma unroll
            for (int mj = 0; mj < 4; ++mj) {
                const uint32_t ta = (uint32_t)(((wj * 4 + mj) * 2 + kt) * 512) + a_off;
                ldsm_x4(ahi[mj], Ahi_b + ta);
                ldsm_x4(alo[mj], Alo_b + ta);
            }
            const uint32_t krow = (uint32_t)(kt * 16 + (lane & 15));
            #pragma unroll
            for (int nj = 0; nj < 4; ++nj) {
                const uint32_t go = (((uint32_t)(wn0g + nj)) ^ (krow & 7u)) << 4;
                ldsm_x2t(bhi[nj], Bhi_b + krow * 256 + go);
                ldsm_x2t(blo[nj], Blo_b + krow * 256 + go);
            }
            #pragma unroll
            for (int mj = 0; mj < 4; ++mj)
                #pragma unroll
                for (int nj = 0; nj < 4; ++nj) {
                    mma_bf16(acc[mj][nj], ahi[mj], bhi[nj]);
                    mma_bf16(acc[mj][nj], ahi[mj], blo[nj]);
                    mma_bf16(acc[mj][nj], alo[mj], bhi[nj]);
                }
        }
        __syncthreads();
    }

    #pragma unroll
    for (int mj = 0; mj < 4; ++mj) {
        const int jr = j0 + wj * 64 + mj * 16 + (lane >> 2);
        #pragma unroll
        for (int nj = 0; nj < 4; ++nj) {
            const int nc = n0 + (w & 3) * 32 + nj * 8 + (lane & 3) * 2;
            float2 v0 = make_float2(acc[mj][nj][0], acc[mj][nj][1]);
            float2 v1 = make_float2(acc[mj][nj][2], acc[mj][nj][3]);
            *(float2*)(C + (size_t)jr * TTBB + nc)       = v0;
            *(float2*)(C + (size_t)(jr + 8) * TTBB + nc) = v1;
        }
    }
}

// ---------------------------------------------------------------------------
// Recurrent kernel: W_hh fragments resident in registers; B fragments
// loaded straight from global (permuted h layout) with LDG.64 .cg.
// 128 CTAs = 64 unit-groups x 2 batch-groups; warp w owns k [w*64, w*64+64).
// ---------------------------------------------------------------------------
template <int LAYER>
__global__ __launch_bounds__(NTH)
void lstm_rec_kernel(const float* __restrict__ W_hh,
                     const float* __restrict__ b_ih,
                     const float* __restrict__ b_hh,
                     const float* __restrict__ xg,
                     float* __restrict__ d_out) {
    extern __shared__ char smem_raw[];
    __nv_bfloat16* W_hi  = (__nv_bfloat16*)smem_raw;        // [kk16][2mt][512B]
    __nv_bfloat16* W_lo  = W_hi + HH * 32;
    float* part   = (float*)(W_lo + HH * 32);               // [8][32][32]
    float* gates  = part + 8 * 32 * 32;                     // [32][32]
    float* c_s    = gates + 32 * 32;                        // [8][32]
    float* bias_s = c_s + 8 * 32;                           // [32]

    const int tid  = threadIdx.x;
    const int ug   = blockIdx.x >> 1;
    const int bg   = blockIdx.x & 1;
    const int lane = tid & 31;
    const int w    = tid >> 5;

    // --- stage + split W_hh into smem tiles (proven layout) ---
    for (int i = tid; i < HH * 32; i += NTH) {
        int kcol = i & 15;
        int r    = (i >> 4) & 15;
        int mt   = (i >> 8) & 1;
        int kk   = i >> 9;            // global k16 index 0..31
        int rr   = mt * 16 + r;
        int gate = rr >> 3, ul = rr & 7;
        int kg   = kk * 16 + kcol;
        int j    = gate * HH + ug * 8 + ul;
        float v = W_hh[(size_t)j * HH + kg];
        __nv_bfloat16 hi, lo;
        split_bf16(v, hi, lo);
        int off = (kk * 2 + mt) * 512
                + r * 32
                + ((((unsigned)kcol >> 3) ^ (((unsigned)r >> 2) & 1u)) << 4)
                + (kcol & 7) * 2;
        *(__nv_bfloat16*)((char*)W_hi + off) = hi;
        *(__nv_bfloat16*)((char*)W_lo + off) = lo;
    }
    if (tid < 32) {
        int gate = tid >> 3, ul = tid & 7;
        int j = gate * HH + ug * 8 + ul;
        bias_s[tid] = b_ih[j] + b_hh[j];
    }
    c_s[tid] = 0.0f;
    {   // zero permuted h buf 0 for our slice
        int col = ug * 8 + (tid >> 5);
        int bgl = bg * 32 + (tid & 31);
        int pk = pk_of(col);
        g_hhi[bgl * HH + pk] = __float2bfloat16_rn(0.0f);
        g_hlo[bgl * HH + pk] = __float2bfloat16_rn(0.0f);
    }
    __syncthreads();

    // --- load A fragments into registers (held for all 512 steps) ---
    const uint32_t sWhi = (uint32_t)__cvta_generic_to_shared(W_hi);
    const uint32_t sWlo = (uint32_t)__cvta_generic_to_shared(W_lo);
    const uint32_t a_off = (uint32_t)((lane & 15) * 32
        + ((((unsigned)lane >> 4) ^ ((((unsigned)lane & 15) >> 2) & 1u)) << 4));
    uint32_t Ahi[2][4][4], Alo[2][4][4];
    #pragma unroll
    for (int kt = 0; kt < 4; ++kt) {
        const int kk = w * 4 + kt;
        #pragma unroll
        for (int mt = 0; mt < 2; ++mt) {
            const uint32_t ta = (uint32_t)((kk * 2 + mt) * 512) + a_off;
            ldsm_x4(Ahi[mt][kt], sWhi + ta);
            ldsm_x4(Alo[mt][kt], sWlo + ta);
        }
    }

    unsigned bar_target = 0;
    if (tid == 0) bar_target = *(volatile unsigned*)&g_bar_epoch[bg];
    grid_barrier(tid, bg, bar_target);

    // xg read slot
    const int xrow = tid >> 3;
    const int xcg  = (tid & 7) << 2;
    const int xj   = (xrow >> 3) * HH + ug * 8 + (xrow & 7);
    const float* xg_base = xg + (size_t)xj * TTBB + bg * 32 + xcg;

    // B lane base (elems): row b, permuted-k
    const int b_elem0 = (bg * 32 + (lane >> 2)) * HH + w * 64 + (lane & 3) * 4;

    for (int t = 0; t < TT; ++t) {
        const float4 xg4 = __ldg((const float4*)(xg_base + t * BB));
        const int hoff = (t & 1) * (HH * BB);

        // --- B fragments straight from L2 (32 x LDG.64 .cg) ---
        uint32_t Bhi[4][4][2], Blo[4][4][2];
        #pragma unroll
        for (int nt = 0; nt < 4; ++nt) {
            #pragma unroll
            for (int kt = 0; kt < 4; ++kt) {
                const int e = hoff + b_elem0 + nt * 8 * HH + kt * 16;
                const uint2 vh = __ldcg((const uint2*)(g_hhi + e));
                const uint2 vl = __ldcg((const uint2*)(g_hlo + e));
                Bhi[kt][nt][0] = vh.x; Bhi[kt][nt][1] = vh.y;
                Blo[kt][nt][0] = vl.x; Blo[kt][nt][1] = vl.y;
            }
        }

        float acc[2][4][4];
        #pragma unroll
        for (int mt = 0; mt < 2; ++mt)
            #pragma unroll
            for (int j = 0; j < 4; ++j)
                #pragma unroll
                for (int q = 0; q < 4; ++q) acc[mt][j][q] = 0.0f;

        #pragma unroll
        for (int kt = 0; kt < 4; ++kt)
            #pragma unroll
            for (int mt = 0; mt < 2; ++mt)
                #pragma unroll
                for (int nt = 0; nt < 4; ++nt) {
                    mma_bf16_2(acc[mt][nt], Ahi[mt][kt], Bhi[kt][nt][0], Bhi[kt][nt][1]);
                    mma_bf16_2(acc[mt][nt], Ahi[mt][kt], Blo[kt][nt][0], Blo[kt][nt][1]);
                    mma_bf16_2(acc[mt][nt], Alo[mt][kt], Bhi[kt][nt][0], Bhi[kt][nt][1]);
                }

        // --- scatter warp partials ---
        {
            const int row0 = lane >> 2;
            const int col0 = (lane & 3) * 2;
            float* pw = part + w * 1024;
            #pragma unroll
            for (int mt = 0; mt < 2; ++mt)
                #pragma unroll
                for (int j = 0; j < 4; ++j) {
                    float* p = pw + (mt * 16 + row0) * 32 + j * 8 + col0;
                    p[0]          = acc[mt][j][0];
                    p[1]          = acc[mt][j][1];
                    p[8 * 32]     = acc[mt][j][2];
                    p[8 * 32 + 1] = acc[mt][j][3];
                }
        }
        __syncthreads();

        // --- reduce 8 partials + xg + bias -> gates ---
        {
            float4 s = make_float4(xg4.x, xg4.y, xg4.z, xg4.w);
            #pragma unroll
            for (int p = 0; p < 8; ++p) {
                const float4 v = *(const float4*)(part + p * 1024 + xrow * 32 + xcg);
                s.x += v.x; s.y += v.y; s.z += v.z; s.w += v.w;
            }
            const float bias = bias_s[xrow];
            *(float4*)(gates + xrow * 32 + xcg) =
                make_float4(s.x + bias, s.y + bias, s.z + bias, s.w + bias);
        }
        __syncthreads();

        // --- cell update ---
        {
            const int ul = tid >> 5;
            const int b  = tid & 31;
            const float gi = gates[(0  + ul) * 32 + b];
            const float gf = gates[(8  + ul) * 32 + b];
            const float gg = gates[(16 + ul) * 32 + b];
            const float go = gates[(24 + ul) * 32 + b];
            const float i_ = 1.0f / (1.0f + expf(-gi));
            const float f_ = 1.0f / (1.0f + expf(-gf));
            const float g_ = tanhf(gg);
            const float o_ = 1.0f / (1.0f + expf(-go));
            const float cn = f_ * c_s[tid] + i_ * g_;
            c_s[tid] = cn;
            const float h = o_ * tanhf(cn);
            const int col = ug * 8 + ul;
            const int bgl = bg * 32 + b;
            __nv_bfloat16 hi, lo;
            split_bf16(h, hi, lo);
            const int pk = pk_of(col);
            const int hdst = ((t + 1) & 1) * (HH * BB) + bgl * HH + pk;
            g_hhi[hdst] = hi;
            g_hlo[hdst] = lo;
            if (LAYER == 0) {
                const size_t oo = (size_t)col * TTBB + t * BB + bgl;
                g_o0hi[oo] = hi;
                g_o0lo[oo] = lo;
            }
            if (t == TT - 1) {
                d_out[64 + LAYER * (BB * HH) + (size_t)bgl * HH + col] = h;
                d_out[64 + 2 * (BB * HH) + LAYER * (BB * HH) + (size_t)bgl * HH + col] = cn;
            }
        }
        grid_barrier(tid, bg, bar_target);
    }
}

// ---------------------------------------------------------------------------
// FC: out[b] = dot(hn1[b,:], fc_w) + fc_b
// ---------------------------------------------------------------------------
__global__ void fc_kernel(const float* __restrict__ fc_w,
                          const float* __restrict__ fc_b,
                          float* __restrict__ d_out) {
    const int b = blockIdx.x;
    const int tid = threadIdx.x;
    const float* h = d_out + 64 + (BB * HH) + (size_t)b * HH;
    float s = 0.0f;
    for (int k = tid; k < HH; k += 128) s += h[k] * fc_w[k];
    #pragma unroll
    for (int off = 16; off > 0; off >>= 1) s += __shfl_down_sync(0xffffffffu, s, off);
    __shared__ float wsum[4];
    if ((tid & 31) == 0) wsum[tid >> 5] = s;
    __syncthreads();
    if (tid == 0) d_out[b] = wsum[0] + wsum[1] + wsum[2] + wsum[3] + fc_b[0];
}

// ---------------------------------------------------------------------------
// Launch
// ---------------------------------------------------------------------------
extern "C" void kernel_launch(void* const* d_in, const int* in_sizes, int n_in,
                              void* d_out, int out_size) {
    const float* x     = (const float*)d_in[0];
    const float* W_ih0 = (const float*)d_in[1];
    const float* W_hh0 = (const float*)d_in[2];
    const float* b_ih0 = (const float*)d_in[3];
    const float* b_hh0 = (const float*)d_in[4];
    const float* W_ih1 = (const float*)d_in[5];
    const float* W_hh1 = (const float*)d_in[6];
    const float* b_ih1 = (const float*)d_in[7];
    const float* b_hh1 = (const float*)d_in[8];
    const float* fc_w  = (const float*)d_in[9];
    const float* fc_b  = (const float*)d_in[10];
    float* out = (float*)d_out;

    __nv_bfloat16 *wih0hi, *wih0lo, *wih1hi, *wih1lo, *xhi, *xlo, *o0hi, *o0lo;
    float *xg0, *xg1;
    cudaGetSymbolAddress((void**)&wih0hi, g_wih0hi);
    cudaGetSymbolAddress((void**)&wih0lo, g_wih0lo);
    cudaGetSymbolAddress((void**)&wih1hi, g_wih1hi);
    cudaGetSymbolAddress((void**)&wih1lo, g_wih1lo);
    cudaGetSymbolAddress((void**)&xhi, g_xhi);
    cudaGetSymbolAddress((void**)&xlo, g_xlo);
    cudaGetSymbolAddress((void**)&o0hi, g_o0hi);
    cudaGetSymbolAddress((void**)&o0lo, g_o0lo);
    cudaGetSymbolAddress((void**)&xg0, g_xg0);
    cudaGetSymbolAddress((void**)&xg1, g_xg1);

    const int smem_tr   = 256 * 65 * 4;
    const int smem_gemm = 65536;
    const int smem_rec  = HH * 32 * 2 * 2                     // W hi+lo
                        + 8 * 32 * 32 * 4 + 32 * 32 * 4 + 8 * 32 * 4 + 32 * 4;

    cudaFuncSetAttribute(transpose_x_kernel,
                         cudaFuncAttributeMaxDynamicSharedMemorySize, smem_tr);
    cudaFuncSetAttribute(gemm_xg_kernel<DD>,
                         cudaFuncAttributeMaxDynamicSharedMemorySize, smem_gemm);
    cudaFuncSetAttribute(gemm_xg_kernel<HH>,
                         cudaFuncAttributeMaxDynamicSharedMemorySize, smem_gemm);
    cudaFuncSetAttribute(lstm_rec_kernel<0>,
                         cudaFuncAttributeMaxDynamicSharedMemorySize, smem_rec);
    cudaFuncSetAttribute(lstm_rec_kernel<1>,
                         cudaFuncAttributeMaxDynamicSharedMemorySize, smem_rec);

    split_w_kernel<<<256, 256>>>(W_ih0, wih0hi, wih0lo, 4 * HH * DD);
    split_w_kernel<<<256, 256>>>(W_ih1, wih1hi, wih1lo, 4 * HH * HH);
    transpose_x_kernel<<<TT, NTH, smem_tr>>>(x);

    dim3 ggrid(TTBB / 128, 16);
    gemm_xg_kernel<DD><<<ggrid, NTH, smem_gemm>>>(wih0hi, wih0lo, xhi, xlo, xg0);
    lstm_rec_kernel<0><<<NCTA, NTH, smem_rec>>>(W_hh0, b_ih0, b_hh0, xg0, out);
    gemm_xg_kernel<HH><<<ggrid, NTH, smem_gemm>>>(wih1hi, wih1lo, o0hi, o0lo, xg1);
    lstm_rec_kernel<1><<<NCTA, NTH, smem_rec>>>(W_hh1, b_ih1, b_hh1, xg1, out);
    fc_kernel<<<BB, 128>>>(fc_w, fc_b, out);
}

// round 12
// speedup vs baseline: 1.2220x; 1.2220x over previous
#include <cuda_runtime.h>
#include <cuda_bf16.h>
#include <cstdint>
#include <math.h>

#define BB    64
#define TT    512
#define DD    256
#define HH    512
#define TTBB  (TT * BB)     // 32768
#define NCTA  128
#define NGRP  64
#define NTH   256

// ---------------------------------------------------------------------------
// Global scratch
// ---------------------------------------------------------------------------
__device__ __nv_bfloat16 g_xhi[DD * TTBB];      // x planes [d][t][b]
__device__ __nv_bfloat16 g_xlo[DD * TTBB];
__device__ __nv_bfloat16 g_o0hi[HH * TTBB];     // layer0 out planes [h][t][b]
__device__ __nv_bfloat16 g_o0lo[HH * TTBB];
__device__ __nv_bfloat16 g_hhi[2 * HH * BB];    // h planes [buf][h][b]
__device__ __nv_bfloat16 g_hlo[2 * HH * BB];
__device__ __nv_bfloat16 g_wih0hi[4 * HH * DD];
__device__ __nv_bfloat16 g_wih0lo[4 * HH * DD];
__device__ __nv_bfloat16 g_wih1hi[4 * HH * HH];
__device__ __nv_bfloat16 g_wih1lo[4 * HH * HH];
__device__ float g_xg0[(size_t)4 * HH * TTBB];
__device__ float g_xg1[(size_t)4 * HH * TTBB];
__device__ unsigned g_bar_count[2];
__device__ unsigned g_bar_epoch[2];

// ---------------------------------------------------------------------------
// Helpers
// ---------------------------------------------------------------------------
__device__ __forceinline__ void ldsm_x4(uint32_t (&r)[4], uint32_t addr) {
    asm volatile("ldmatrix.sync.aligned.m8n8.x4.shared.b16 {%0,%1,%2,%3}, [%4];\n"
                 : "=r"(r[0]), "=r"(r[1]), "=r"(r[2]), "=r"(r[3]) : "r"(addr));
}
__device__ __forceinline__ void ldsm_x2t(uint32_t (&r)[2], uint32_t addr) {
    asm volatile("ldmatrix.sync.aligned.m8n8.x2.trans.shared.b16 {%0,%1}, [%2];\n"
                 : "=r"(r[0]), "=r"(r[1]) : "r"(addr));
}
__device__ __forceinline__ void mma_bf16(float (&d)[4], const uint32_t (&a)[4],
                                         const uint32_t (&b)[2]) {
    asm volatile("mma.sync.aligned.m16n8k16.row.col.f32.bf16.bf16.f32 "
                 "{%0,%1,%2,%3}, {%4,%5,%6,%7}, {%8,%9}, {%0,%1,%2,%3};\n"
                 : "+f"(d[0]), "+f"(d[1]), "+f"(d[2]), "+f"(d[3])
                 : "r"(a[0]), "r"(a[1]), "r"(a[2]), "r"(a[3]),
                   "r"(b[0]), "r"(b[1]));
}
__device__ __forceinline__ void split_bf16(float v, __nv_bfloat16& hi, __nv_bfloat16& lo) {
    hi = __float2bfloat16_rn(v);
    lo = __float2bfloat16_rn(v - __bfloat162float(hi));
}
__device__ __forceinline__ void cp_async16(uint32_t dst, const void* src) {
    asm volatile("cp.async.cg.shared.global [%0], [%1], 16;\n" :: "r"(dst), "l"(src));
}
__device__ __forceinline__ void cp_commit() {
    asm volatile("cp.async.commit_group;\n");
}
template <int N>
__device__ __forceinline__ void cp_wait() {
    asm volatile("cp.async.wait_group %0;\n" :: "n"(N));
}

// ---------------------------------------------------------------------------
// MUFU-free activation math
// ---------------------------------------------------------------------------
__device__ __forceinline__ float fast_exp(float x) {
    // |x| <= ~30 guaranteed by caller clamps
    float z = x * 1.4426950408889634f;
    float nf = rintf(z);
    float f = z - nf;
    float p = 1.535336188319500e-4f;
    p = fmaf(p, f, 1.339887440266574e-3f);
    p = fmaf(p, f, 9.618437357674640e-3f);
    p = fmaf(p, f, 5.550332471162809e-2f);
    p = fmaf(p, f, 2.402264791363012e-1f);
    p = fmaf(p, f, 6.931472028550421e-1f);
    p = fmaf(p, f, 1.0f);
    int n = (int)nf;
    return p * __int_as_float((n + 127) << 23);
}
__device__ __forceinline__ float fast_rcp(float x) {
    // x >= 1 here (denominators 1+e); Newton x3 from bit-trick seed
    float y = __int_as_float(0x7EF311C3 - __float_as_int(x));
    y = y * (2.0f - x * y);
    y = y * (2.0f - x * y);
    y = y * (2.0f - x * y);
    return y;
}
__device__ __forceinline__ float fast_sigmoid(float x) {
    x = fminf(30.0f, fmaxf(-30.0f, x));
    return fast_rcp(1.0f + fast_exp(-x));
}
__device__ __forceinline__ float fast_tanh(float x) {
    x = fminf(15.0f, fmaxf(-15.0f, x));
    float e = fast_exp(2.0f * x);
    return (e - 1.0f) * fast_rcp(e + 1.0f);
}

// ---------------------------------------------------------------------------
// Grouped grid barrier (64 CTAs per group, all co-resident)
// ---------------------------------------------------------------------------
__device__ __forceinline__ void grid_barrier(int tid, int grp, unsigned& target) {
    __threadfence();
    __syncthreads();
    target += 1;
    if (tid == 0) {
        unsigned old = atomicAdd(&g_bar_count[grp], 1u);
        if (old == NGRP - 1) {
            atomicExch(&g_bar_count[grp], 0u);
            __threadfence();
            atomicAdd(&g_bar_epoch[grp], 1u);
        } else {
            while ((int)(*(volatile unsigned*)&g_bar_epoch[grp] - target) < 0) {
                __nanosleep(32);
            }
            __threadfence();
        }
    }
    __syncthreads();
}

// ---------------------------------------------------------------------------
// Split fp32 weights into bf16 hi/lo planes
// ---------------------------------------------------------------------------
__global__ void split_w_kernel(const float* __restrict__ W,
                               __nv_bfloat16* __restrict__ hi,
                               __nv_bfloat16* __restrict__ lo, int n) {
    for (int i = blockIdx.x * blockDim.x + threadIdx.x; i < n; i += gridDim.x * blockDim.x) {
        __nv_bfloat16 h, l;
        split_bf16(W[i], h, l);
        hi[i] = h;
        lo[i] = l;
    }
}

// ---------------------------------------------------------------------------
// Transpose + split x: [b][t][d] -> planes [d][t][b]
// ---------------------------------------------------------------------------
__global__ void transpose_x_kernel(const float* __restrict__ x) {
    extern __shared__ float sm[];  // [256][65]
    const int t = blockIdx.x;
    const int tid = threadIdx.x;
    for (int i = tid; i < BB * DD; i += NTH) {
        int b = i >> 8;
        int d = i & 255;
        sm[d * 65 + b] = x[(size_t)b * (TT * DD) + (size_t)t * DD + d];
    }
    __syncthreads();
    for (int i = tid; i < DD * BB; i += NTH) {
        int d = i >> 6;
        int b = i & 63;
        float v = sm[d * 65 + b];
        __nv_bfloat16 hi, lo;
        split_bf16(v, hi, lo);
        const size_t idx = (size_t)d * TTBB + t * BB + b;
        g_xhi[idx] = hi;
        g_xlo[idx] = lo;
    }
}

// ---------------------------------------------------------------------------
// Bulk GEMM (unchanged, proven: tensor 62%)
// ---------------------------------------------------------------------------
template <int K>
__global__ __launch_bounds__(NTH)
void gemm_xg_kernel(const __nv_bfloat16* __restrict__ Whi,
                    const __nv_bfloat16* __restrict__ Wlo,
                    const __nv_bfloat16* __restrict__ Xhi,
                    const __nv_bfloat16* __restrict__ Xlo,
                    float* __restrict__ C) {
    constexpr int NKC = K / 32;
    extern __shared__ char sm_raw[];
    const uint32_t sbase = (uint32_t)__cvta_generic_to_shared(sm_raw);

    const int tid  = threadIdx.x;
    const int lane = tid & 31;
    const int w    = tid >> 5;
    const int wj   = w >> 2;
    const int wn0g = (w & 3) * 4;
    const int j0   = blockIdx.y * 128;
    const int n0   = blockIdx.x * 128;

    auto stage = [&](int kc, int buf) {
        const uint32_t bb = sbase + buf * 32768;
        #pragma unroll
        for (int q = 0; q < 4; ++q) {
            int idx = tid + q * 256;
            int p   = idx >> 9;
            int rem = idx & 511;
            int jl  = rem >> 2;
            int kh  = (rem >> 1) & 1;
            int g   = rem & 1;
            const __nv_bfloat16* src = (p ? Wlo : Whi)
                + (size_t)(j0 + jl) * K + kc * 32 + kh * 16 + g * 8;
            uint32_t dst = bb + p * 8192
                + (((jl >> 4) * 2 + kh) * 512)
                + (jl & 15) * 32
                + ((((unsigned)g) ^ (((unsigned)jl >> 2) & 1u)) << 4);
            cp_async16(dst, src);
        }
        #pragma unroll
        for (int q = 0; q < 4; ++q) {
            int idx = tid + q * 256;
            int p   = idx >> 9;
            int rem = idx & 511;
            int k   = rem >> 4;
            int g   = rem & 15;
            const __nv_bfloat16* src = (p ? Xlo : Xhi)
                + (size_t)(kc * 32 + k) * TTBB + n0 + g * 8;
            uint32_t dst = bb + 16384 + p * 8192 + k * 256
                + ((((unsigned)g) ^ ((unsigned)k & 7u)) << 4);
            cp_async16(dst, src);
        }
        cp_commit();
    };

    const uint32_t a_off = (uint32_t)((lane & 15) * 32
        + ((((unsigned)lane >> 4) ^ ((((unsigned)lane & 15) >> 2) & 1u)) << 4));

    float acc[4][4][4];
    #pragma unroll
    for (int mj = 0; mj < 4; ++mj)
        #pragma unroll
        for (int nj = 0; nj < 4; ++nj)
            #pragma unroll
            for (int q = 0; q < 4; ++q) acc[mj][nj][q] = 0.0f;

    stage(0, 0);
    for (int kc = 0; kc < NKC; ++kc) {
        if (kc + 1 < NKC) {
            stage(kc + 1, (kc + 1) & 1);
            cp_wait<1>();
        } else {
            cp_wait<0>();
        }
        __syncthreads();

        const uint32_t bb = sbase + (kc & 1) * 32768;
        const uint32_t Ahi_b = bb, Alo_b = bb + 8192;
        const uint32_t Bhi_b = bb + 16384, Blo_b = bb + 24576;

        #pragma unroll
        for (int kt = 0; kt < 2; ++kt) {
            uint32_t ahi[4][4], alo[4][4], bhi[4][2], blo[4][2];
            #pragma unroll
            for (int mj = 0; mj < 4; ++mj) {
                const uint32_t ta = (uint32_t)(((wj * 4 + mj) * 2 + kt) * 512) + a_off;
                ldsm_x4(ahi[mj], Ahi_b + ta);
                ldsm_x4(alo[mj], Alo_b + ta);
            }
            const uint32_t krow = (uint32_t)(kt * 16 + (lane & 15));
            #pragma unroll
            for (int nj = 0; nj < 4; ++nj) {
                const uint32_t go = (((uint32_t)(wn0g + nj)) ^ (krow & 7u)) << 4;
                ldsm_x2t(bhi[nj], Bhi_b + krow * 256 + go);
                ldsm_x2t(blo[nj], Blo_b + krow * 256 + go);
            }
            #pragma unroll
            for (int mj = 0; mj < 4; ++mj)
                #pragma unroll
                for (int nj = 0; nj < 4; ++nj) {
                    mma_bf16(acc[mj][nj], ahi[mj], bhi[nj]);
                    mma_bf16(acc[mj][nj], ahi[mj], blo[nj]);
                    mma_bf16(acc[mj][nj], alo[mj], bhi[nj]);
                }
        }
        __syncthreads();
    }

    #pragma unroll
    for (int mj = 0; mj < 4; ++mj) {
        const int jr = j0 + wj * 64 + mj * 16 + (lane >> 2);
        #pragma unroll
        for (int nj = 0; nj < 4; ++nj) {
            const int nc = n0 + (w & 3) * 32 + nj * 8 + (lane & 3) * 2;
            float2 v0 = make_float2(acc[mj][nj][0], acc[mj][nj][1]);
            float2 v1 = make_float2(acc[mj][nj][2], acc[mj][nj][3]);
            *(float2*)(C + (size_t)jr * TTBB + nc)       = v0;
            *(float2*)(C + (size_t)(jr + 8) * TTBB + nc) = v1;
        }
    }
}

// ---------------------------------------------------------------------------
// Recurrent kernel: A (W_hh) fragments in registers; B staged via cp.async
// into swizzled smem (R10-proven layout); MUFU-free activations; fused
// reduce+cell. 128 CTAs = 64 ug x 2 bg; warp w owns k [w*64, w*64+64).
// ---------------------------------------------------------------------------
template <int LAYER>
__global__ __launch_bounds__(NTH)
void lstm_rec_kernel(const float* __restrict__ W_hh,
                     const float* __restrict__ b_ih,
                     const float* __restrict__ b_hh,
                     const float* __restrict__ xg,
                     float* __restrict__ d_out) {
    extern __shared__ char smem_raw[];
    __nv_bfloat16* W_hi  = (__nv_bfloat16*)smem_raw;        // [kk16*2mt][512B]
    __nv_bfloat16* W_lo  = W_hi + HH * 32;
    __nv_bfloat16* st_hi = W_lo + HH * 32;                  // [512k][32b] swizzled
    __nv_bfloat16* st_lo = st_hi + HH * 32;
    float* part   = (float*)(st_lo + HH * 32);              // [8][32][32]
    float* c_s    = part + 8 * 32 * 32;                     // [8][32]
    float* bias_s = c_s + 8 * 32;                           // [32]

    const int tid  = threadIdx.x;
    const int ug   = blockIdx.x >> 1;
    const int bg   = blockIdx.x & 1;
    const int lane = tid & 31;
    const int w    = tid >> 5;

    // --- stage + split W_hh into smem tiles (proven layout) ---
    for (int i = tid; i < HH * 32; i += NTH) {
        int kcol = i & 15;
        int r    = (i >> 4) & 15;
        int mt   = (i >> 8) & 1;
        int kk   = i >> 9;
        int rr   = mt * 16 + r;
        int gate = rr >> 3, ul = rr & 7;
        int kg   = kk * 16 + kcol;
        int j    = gate * HH + ug * 8 + ul;
        float v = W_hh[(size_t)j * HH + kg];
        __nv_bfloat16 hi, lo;
        split_bf16(v, hi, lo);
        int off = (kk * 2 + mt) * 512
                + r * 32
                + ((((unsigned)kcol >> 3) ^ (((unsigned)r >> 2) & 1u)) << 4)
                + (kcol & 7) * 2;
        *(__nv_bfloat16*)((char*)W_hi + off) = hi;
        *(__nv_bfloat16*)((char*)W_lo + off) = lo;
    }
    if (tid < 32) {
        int gate = tid >> 3, ul = tid & 7;
        int j = gate * HH + ug * 8 + ul;
        bias_s[tid] = b_ih[j] + b_hh[j];
    }
    c_s[tid] = 0.0f;
    {   // zero h buf 0 for our slice
        int col = ug * 8 + (tid >> 5);
        int bgl = bg * 32 + (tid & 31);
        g_hhi[col * BB + bgl] = __float2bfloat16_rn(0.0f);
        g_hlo[col * BB + bgl] = __float2bfloat16_rn(0.0f);
    }
    __syncthreads();

    // --- A fragments into registers (held for all 512 steps) ---
    const uint32_t sWhi = (uint32_t)__cvta_generic_to_shared(W_hi);
    const uint32_t sWlo = (uint32_t)__cvta_generic_to_shared(W_lo);
    const uint32_t a_off = (uint32_t)((lane & 15) * 32
        + ((((unsigned)lane >> 4) ^ ((((unsigned)lane & 15) >> 2) & 1u)) << 4));
    uint32_t Ahi[2][4][4], Alo[2][4][4];
    #pragma unroll
    for (int kt = 0; kt < 4; ++kt) {
        const int kk = w * 4 + kt;
        #pragma unroll
        for (int mt = 0; mt < 2; ++mt) {
            const uint32_t ta = (uint32_t)((kk * 2 + mt) * 512) + a_off;
            ldsm_x4(Ahi[mt][kt], sWhi + ta);
            ldsm_x4(Alo[mt][kt], sWlo + ta);
        }
    }

    unsigned bar_target = 0;
    if (tid == 0) bar_target = *(volatile unsigned*)&g_bar_epoch[bg];
    grid_barrier(tid, bg, bar_target);

    const uint32_t sShi = (uint32_t)__cvta_generic_to_shared(st_hi);
    const uint32_t sSlo = (uint32_t)__cvta_generic_to_shared(st_lo);

    // cell identity for fused epilogue: warp = unit (ul), lane = batch (b)
    const int ul  = w;
    const int bcl = lane;
    const int bgl = bg * 32 + bcl;
    const size_t xg_cell = (size_t)(ug * 8 + ul) * TTBB + bgl;   // + gate*HH*TTBB

    for (int t = 0; t < TT; ++t) {
        // xg prefetch for this thread's cell (4 gates, coalesced per warp)
        float xgv[4];
        #pragma unroll
        for (int gate = 0; gate < 4; ++gate)
            xgv[gate] = __ldg(xg + (size_t)gate * (HH * TTBB) + xg_cell + (size_t)t * BB);

        // --- stage h via cp.async (zero reg round-trip) ---
        const int hoff = (t & 1) * (HH * BB);
        #pragma unroll
        for (int q = 0; q < 8; ++q) {
            int s = tid + q * 256;
            int k = s >> 2, g = s & 3;
            const int so = hoff + k * BB + bg * 32 + g * 8;
            uint32_t doff = (uint32_t)(k * 64 + ((((unsigned)g) ^ (((unsigned)k >> 1) & 3u)) << 4));
            cp_async16(sShi + doff, g_hhi + so);
            cp_async16(sSlo + doff, g_hlo + so);
        }
        cp_commit();
        cp_wait<0>();
        __syncthreads();

        // --- MMA: A from regs, B via ldsm from staged smem ---
        float acc[2][4][4];
        #pragma unroll
        for (int mt = 0; mt < 2; ++mt)
            #pragma unroll
            for (int j = 0; j < 4; ++j)
                #pragma unroll
                for (int q = 0; q < 4; ++q) acc[mt][j][q] = 0.0f;

        #pragma unroll
        for (int kt = 0; kt < 4; ++kt) {
            const uint32_t kabs = (uint32_t)((w * 4 + kt) * 16 + (lane & 15));
            const uint32_t bswz = (kabs >> 1) & 3u;
            const uint32_t brow = kabs * 64;
            uint32_t bhi[4][2], blo[4][2];
            #pragma unroll
            for (int j = 0; j < 4; ++j) {
                const uint32_t go = (((uint32_t)j) ^ bswz) << 4;
                ldsm_x2t(bhi[j], sShi + brow + go);
                ldsm_x2t(blo[j], sSlo + brow + go);
            }
            #pragma unroll
            for (int mt = 0; mt < 2; ++mt)
                #pragma unroll
                for (int j = 0; j < 4; ++j) {
                    mma_bf16(acc[mt][j], Ahi[mt][kt], bhi[j]);
                    mma_bf16(acc[mt][j], Ahi[mt][kt], blo[j]);
                    mma_bf16(acc[mt][j], Alo[mt][kt], bhi[j]);
                }
        }

        // --- scatter warp partials ---
        {
            const int row0 = lane >> 2;
            const int col0 = (lane & 3) * 2;
            float* pw = part + w * 1024;
            #pragma unroll
            for (int mt = 0; mt < 2; ++mt)
                #pragma unroll
                for (int j = 0; j < 4; ++j) {
                    float* p = pw + (mt * 16 + row0) * 32 + j * 8 + col0;
                    p[0]          = acc[mt][j][0];
                    p[1]          = acc[mt][j][1];
                    p[8 * 32]     = acc[mt][j][2];
                    p[8 * 32 + 1] = acc[mt][j][3];
                }
        }
        __syncthreads();

        // --- fused reduce + cell update (this thread's cell = (ul, bcl)) ---
        {
            float gsum[4];
            #pragma unroll
            for (int gate = 0; gate < 4; ++gate) {
                const int rr = gate * 8 + ul;
                float s = xgv[gate] + bias_s[rr];
                #pragma unroll
                for (int p = 0; p < 8; ++p)
                    s += part[p * 1024 + rr * 32 + bcl];
                gsum[gate] = s;
            }
            const float i_ = fast_sigmoid(gsum[0]);
            const float f_ = fast_sigmoid(gsum[1]);
            const float g_ = fast_tanh(gsum[2]);
            const float o_ = fast_sigmoid(gsum[3]);
            const float cn = f_ * c_s[tid] + i_ * g_;
            c_s[tid] = cn;
            const float h = o_ * fast_tanh(cn);
            const int col = ug * 8 + ul;
            __nv_bfloat16 hi, lo;
            split_bf16(h, hi, lo);
            const int hdst = ((t + 1) & 1) * (HH * BB) + col * BB + bgl;
            g_hhi[hdst] = hi;
            g_hlo[hdst] = lo;
            if (LAYER == 0) {
                const size_t oo = (size_t)col * TTBB + t * BB + bgl;
                g_o0hi[oo] = hi;
                g_o0lo[oo] = lo;
            }
            if (t == TT - 1) {
                d_out[64 + LAYER * (BB * HH) + (size_t)bgl * HH + col] = h;
                d_out[64 + 2 * (BB * HH) + LAYER * (BB * HH) + (size_t)bgl * HH + col] = cn;
            }
        }
        grid_barrier(tid, bg, bar_target);
    }
}

// ---------------------------------------------------------------------------
// FC: out[b] = dot(hn1[b,:], fc_w) + fc_b
// ---------------------------------------------------------------------------
__global__ void fc_kernel(const float* __restrict__ fc_w,
                          const float* __restrict__ fc_b,
                          float* __restrict__ d_out) {
    const int b = blockIdx.x;
    const int tid = threadIdx.x;
    const float* h = d_out + 64 + (BB * HH) + (size_t)b * HH;
    float s = 0.0f;
    for (int k = tid; k < HH; k += 128) s += h[k] * fc_w[k];
    #pragma unroll
    for (int off = 16; off > 0; off >>= 1) s += __shfl_down_sync(0xffffffffu, s, off);
    __shared__ float wsum[4];
    if ((tid & 31) == 0) wsum[tid >> 5] = s;
    __syncthreads();
    if (tid == 0) d_out[b] = wsum[0] + wsum[1] + wsum[2] + wsum[3] + fc_b[0];
}

// ---------------------------------------------------------------------------
// Launch
// ---------------------------------------------------------------------------
extern "C" void kernel_launch(void* const* d_in, const int* in_sizes, int n_in,
                              void* d_out, int out_size) {
    const float* x     = (const float*)d_in[0];
    const float* W_ih0 = (const float*)d_in[1];
    const float* W_hh0 = (const float*)d_in[2];
    const float* b_ih0 = (const float*)d_in[3];
    const float* b_hh0 = (const float*)d_in[4];
    const float* W_ih1 = (const float*)d_in[5];
    const float* W_hh1 = (const float*)d_in[6];
    const float* b_ih1 = (const float*)d_in[7];
    const float* b_hh1 = (const float*)d_in[8];
    const float* fc_w  = (const float*)d_in[9];
    const float* fc_b  = (const float*)d_in[10];
    float* out = (float*)d_out;

    __nv_bfloat16 *wih0hi, *wih0lo, *wih1hi, *wih1lo, *xhi, *xlo, *o0hi, *o0lo;
    float *xg0, *xg1;
    cudaGetSymbolAddress((void**)&wih0hi, g_wih0hi);
    cudaGetSymbolAddress((void**)&wih0lo, g_wih0lo);
    cudaGetSymbolAddress((void**)&wih1hi, g_wih1hi);
    cudaGetSymbolAddress((void**)&wih1lo, g_wih1lo);
    cudaGetSymbolAddress((void**)&xhi, g_xhi);
    cudaGetSymbolAddress((void**)&xlo, g_xlo);
    cudaGetSymbolAddress((void**)&o0hi, g_o0hi);
    cudaGetSymbolAddress((void**)&o0lo, g_o0lo);
    cudaGetSymbolAddress((void**)&xg0, g_xg0);
    cudaGetSymbolAddress((void**)&xg1, g_xg1);

    const int smem_tr   = 256 * 65 * 4;
    const int smem_gemm = 65536;
    const int smem_rec  = HH * 32 * 2 * 2        // W hi+lo
                        + HH * 32 * 2 * 2        // stage hi+lo (wait: HH*32 elems*2B*2planes)
                        + 8 * 32 * 32 * 4 + 8 * 32 * 4 + 32 * 4;

    cudaFuncSetAttribute(transpose_x_kernel,
                         cudaFuncAttributeMaxDynamicSharedMemorySize, smem_tr);
    cudaFuncSetAttribute(gemm_xg_kernel<DD>,
                         cudaFuncAttributeMaxDynamicSharedMemorySize, smem_gemm);
    cudaFuncSetAttribute(gemm_xg_kernel<HH>,
                         cudaFuncAttributeMaxDynamicSharedMemorySize, smem_gemm);
    cudaFuncSetAttribute(lstm_rec_kernel<0>,
                         cudaFuncAttributeMaxDynamicSharedMemorySize, smem_rec);
    cudaFuncSetAttribute(lstm_rec_kernel<1>,
                         cudaFuncAttributeMaxDynamicSharedMemorySize, smem_rec);

    split_w_kernel<<<256, 256>>>(W_ih0, wih0hi, wih0lo, 4 * HH * DD);
    split_w_kernel<<<256, 256>>>(W_ih1, wih1hi, wih1lo, 4 * HH * HH);
    transpose_x_kernel<<<TT, NTH, smem_tr>>>(x);

    dim3 ggrid(TTBB / 128, 16);
    gemm_xg_kernel<DD><<<ggrid, NTH, smem_gemm>>>(wih0hi, wih0lo, xhi, xlo, xg0);
    lstm_rec_kernel<0><<<NCTA, NTH, smem_rec>>>(W_hh0, b_ih0, b_hh0, xg0, out);
    gemm_xg_kernel<HH><<<ggrid, NTH, smem_gemm>>>(wih1hi, wih1lo, o0hi, o0lo, xg1);
    lstm_rec_kernel<1><<<NCTA, NTH, smem_rec>>>(W_hh1, b_ih1, b_hh1, xg1, out);
    fc_kernel<<<BB, 128>>>(fc_w, fc_b, out);
}